// round 3
// baseline (speedup 1.0000x reference)
#include <cuda_runtime.h>
#include <cstdint>

// Problem shape (fixed for this instance)
#define B_    16
#define N_    4096
#define S_    1024
#define C2_   256
#define C1_   128
#define CIN_  384      // C2_ + C1_
#define M1_   256
#define M2_   128
#define MROWS (B_ * N_)   // 65536

// ---------------------------------------------------------------------------
// Scratch (static __device__ globals — sanctioned alternative to cudaMalloc)
// ---------------------------------------------------------------------------
__device__ float g_x [(size_t)MROWS * CIN_];   // concat(interp_feat, skip)  ~100.7 MB
__device__ float g_y1[(size_t)MROWS * M1_];    // raw conv1 output            ~67.1 MB
__device__ float g_sum1[M1_], g_sq1[M1_], g_s1[M1_], g_t1[M1_];
__device__ float g_sum2[M2_], g_sq2[M2_], g_s2[M2_], g_t2[M2_];

// ---------------------------------------------------------------------------
// f32x2 packed-FMA helpers (FFMA2: 2x fp32 throughput on sm_103a)
// ---------------------------------------------------------------------------
typedef unsigned long long ull;

__device__ __forceinline__ ull fma2(ull a, ull b, ull c) {
    ull d;
    asm("fma.rn.f32x2 %0, %1, %2, %3;" : "=l"(d) : "l"(a), "l"(b), "l"(c));
    return d;
}
__device__ __forceinline__ ull splat2(float x) {
    ull d;
    asm("mov.b64 %0, {%1, %2};" : "=l"(d) : "f"(x), "f"(x));
    return d;
}
__device__ __forceinline__ float2 unpk2(ull v) {
    float2 r;
    asm("mov.b64 {%0, %1}, %2;" : "=f"(r.x), "=f"(r.y) : "l"(v));
    return r;
}

// ---------------------------------------------------------------------------
// Kernel 0: zero the BN stat accumulators (must run every launch/replay)
// ---------------------------------------------------------------------------
__global__ void zero_stats_kernel() {
    int i = threadIdx.x;
    if (i < M1_) { g_sum1[i] = 0.f; g_sq1[i] = 0.f; }
    if (i < M2_) { g_sum2[i] = 0.f; g_sq2[i] = 0.f; }
}

// ---------------------------------------------------------------------------
// Kernel 1: 3-NN interpolation + concat -> g_x  [MROWS, 384]
// Block: 128 threads handles 128 target points of one batch.
// ---------------------------------------------------------------------------
__global__ void interp_concat_kernel(const float* __restrict__ txyz,
                                     const float* __restrict__ sxyz,
                                     const float* __restrict__ sfeat,
                                     const float* __restrict__ skip)
{
    __shared__ float4 s_src[S_];      // (x, y, z, |s|^2)  16 KB
    __shared__ float  s_w[3][128];
    __shared__ int    s_i[3][128];

    const int b   = blockIdx.y;
    const int p0  = blockIdx.x * 128;
    const int tid = threadIdx.x;

    const float* sx = sxyz + (size_t)b * S_ * 3;
    for (int i = tid; i < S_; i += 128) {
        float x = sx[i * 3 + 0], y = sx[i * 3 + 1], z = sx[i * 3 + 2];
        s_src[i] = make_float4(x, y, z, x * x + y * y + z * z);
    }
    __syncthreads();

    // ---- phase 1: top-3 smallest dist2 (same expansion as reference) ----
    const int n = p0 + tid;
    const float* tp = txyz + ((size_t)b * N_ + n) * 3;
    const float tx0 = tp[0], ty0 = tp[1], tz0 = tp[2];
    const float q2 = tx0 * tx0 + ty0 * ty0 + tz0 * tz0;

    float d0 = 3.4e38f, d1 = 3.4e38f, d2 = 3.4e38f;
    int   i0 = 0, i1 = 0, i2 = 0;
    #pragma unroll 4
    for (int s = 0; s < S_; ++s) {
        float4 v = s_src[s];
        float cr   = tx0 * v.x + ty0 * v.y + tz0 * v.z;
        float dist = fmaxf(q2 + v.w - 2.f * cr, 0.f);
        if (dist < d2) {
            if (dist < d1) {
                d2 = d1; i2 = i1;
                if (dist < d0) { d1 = d0; i1 = i0; d0 = dist; i0 = s; }
                else           { d1 = dist; i1 = s; }
            } else { d2 = dist; i2 = s; }
        }
    }

    // exact d2 recompute + inverse-distance weights (matches reference)
    int   ii[3] = { i0, i1, i2 };
    float w[3];
    float wsum = 0.f;
    #pragma unroll
    for (int k = 0; k < 3; ++k) {
        float4 v = s_src[ii[k]];
        float dx = tx0 - v.x, dy = ty0 - v.y, dz = tz0 - v.z;
        float dd = dx * dx + dy * dy + dz * dz;
        w[k] = 1.f / (dd + 1e-8f);
        wsum += w[k];
    }
    float inv = 1.f / wsum;
    #pragma unroll
    for (int k = 0; k < 3; ++k) { s_w[k][tid] = w[k] * inv; s_i[k][tid] = ii[k]; }
    __syncthreads();

    // ---- phase 2: coalesced gather of features + skip concat ----
    const float* F = sfeat + (size_t)b * S_ * C2_;
    for (int p = 0; p < 128; ++p) {
        const float w0 = s_w[0][p], w1 = s_w[1][p], w2 = s_w[2][p];
        const float* f0 = F + (size_t)s_i[0][p] * C2_;
        const float* f1 = F + (size_t)s_i[1][p] * C2_;
        const float* f2 = F + (size_t)s_i[2][p] * C2_;
        const size_t row = (size_t)b * N_ + p0 + p;
        float* xr = g_x + row * CIN_;

        int c = tid;
        xr[c] = w0 * f0[c] + w1 * f1[c] + w2 * f2[c];
        c = tid + 128;
        xr[c] = w0 * f0[c] + w1 * f1[c] + w2 * f2[c];
        xr[256 + tid] = skip[row * C1_ + tid];
    }
}

// ---------------------------------------------------------------------------
// Kernel 2/4: GEMM  C[M, NOUT] = A[M, K] * W[NOUT, K]^T  with fused:
//   - SECOND: A-load transform a = relu(a * s1[k] + t1[k])  (BN1 + ReLU)
//   - epilogue: per-output-channel sum / sumsq accumulation (BN stats)
// Tiling: 128x128x16 block tile, 256 threads, 8x8 per thread via f32x2.
// ---------------------------------------------------------------------------
template <bool SECOND>
__global__ void __launch_bounds__(256, 2)
gemm_bn_kernel(const float* __restrict__ W, float* __restrict__ outp)
{
    constexpr int K    = SECOND ? M1_ : CIN_;
    constexpr int NOUT = SECOND ? M2_ : M1_;

    const float* A   = SECOND ? g_y1 : g_x;
    float* C         = SECOND ? outp : g_y1;
    float* gsum      = SECOND ? g_sum2 : g_sum1;
    float* gsq       = SECOND ? g_sq2  : g_sq1;

    __shared__ float As[16][132];
    __shared__ float Bs[16][132];
    __shared__ float redsum[128], redsq[128];
    __shared__ float s_sc[SECOND ? M1_ : 1];
    __shared__ float s_sh[SECOND ? M1_ : 1];

    const int tid = threadIdx.x;
    const int tx  = tid & 15;
    const int ty  = tid >> 4;
    const size_t m0 = (size_t)blockIdx.y * 128;
    const int    n0 = blockIdx.x * 128;

    if (tid < 128) { redsum[tid] = 0.f; redsq[tid] = 0.f; }
    if (SECOND) {
        if (tid < K) { s_sc[tid] = g_s1[tid]; s_sh[tid] = g_t1[tid]; }
    }
    __syncthreads();

    const int lr = tid >> 2;         // 0..63
    const int lc = (tid & 3) << 2;   // 0,4,8,12

    const float* Ab = A + m0 * K;
    const float* Bb = W + (size_t)n0 * K;

    ull acc[8][4];
    #pragma unroll
    for (int i = 0; i < 8; ++i)
        #pragma unroll
        for (int j = 0; j < 4; ++j) acc[i][j] = 0ull;

    for (int k0 = 0; k0 < K; k0 += 16) {
        #pragma unroll
        for (int h = 0; h < 2; ++h) {
            const int r = lr + h * 64;
            float4 va = *(const float4*)(Ab + (size_t)r * K + (k0 + lc));
            if (SECOND) {
                va.x = fmaxf(fmaf(va.x, s_sc[k0 + lc + 0], s_sh[k0 + lc + 0]), 0.f);
                va.y = fmaxf(fmaf(va.y, s_sc[k0 + lc + 1], s_sh[k0 + lc + 1]), 0.f);
                va.z = fmaxf(fmaf(va.z, s_sc[k0 + lc + 2], s_sh[k0 + lc + 2]), 0.f);
                va.w = fmaxf(fmaf(va.w, s_sc[k0 + lc + 3], s_sh[k0 + lc + 3]), 0.f);
            }
            As[lc + 0][r] = va.x; As[lc + 1][r] = va.y;
            As[lc + 2][r] = va.z; As[lc + 3][r] = va.w;
            float4 vb = *(const float4*)(Bb + (size_t)r * K + (k0 + lc));
            Bs[lc + 0][r] = vb.x; Bs[lc + 1][r] = vb.y;
            Bs[lc + 2][r] = vb.z; Bs[lc + 3][r] = vb.w;
        }
        __syncthreads();

        #pragma unroll
        for (int kk = 0; kk < 16; ++kk) {
            const float* ap = &As[kk][ty * 8];
            float4 a0 = *(const float4*)(ap);
            float4 a1 = *(const float4*)(ap + 4);
            ull av[8] = { splat2(a0.x), splat2(a0.y), splat2(a0.z), splat2(a0.w),
                          splat2(a1.x), splat2(a1.y), splat2(a1.z), splat2(a1.w) };
            const ulonglong2* bp = (const ulonglong2*)&Bs[kk][tx * 8];
            ulonglong2 bq0 = bp[0], bq1 = bp[1];
            #pragma unroll
            for (int i = 0; i < 8; ++i) {
                acc[i][0] = fma2(av[i], bq0.x, acc[i][0]);
                acc[i][1] = fma2(av[i], bq0.y, acc[i][1]);
                acc[i][2] = fma2(av[i], bq1.x, acc[i][2]);
                acc[i][3] = fma2(av[i], bq1.y, acc[i][3]);
            }
        }
        __syncthreads();
    }

    // ---- epilogue: store + per-channel stats ----
    float csum[8] = {0, 0, 0, 0, 0, 0, 0, 0};
    float csq [8] = {0, 0, 0, 0, 0, 0, 0, 0};
    #pragma unroll
    for (int i = 0; i < 8; ++i) {
        float vals[8];
        #pragma unroll
        for (int j = 0; j < 4; ++j) {
            float2 u = unpk2(acc[i][j]);
            vals[2 * j + 0] = u.x;
            vals[2 * j + 1] = u.y;
        }
        const size_t row = m0 + (size_t)ty * 8 + i;
        float4* op = (float4*)(C + row * NOUT + (n0 + tx * 8));
        op[0] = make_float4(vals[0], vals[1], vals[2], vals[3]);
        op[1] = make_float4(vals[4], vals[5], vals[6], vals[7]);
        #pragma unroll
        for (int j = 0; j < 8; ++j) {
            csum[j] += vals[j];
            csq [j] += vals[j] * vals[j];
        }
    }
    #pragma unroll
    for (int j = 0; j < 8; ++j) {
        atomicAdd(&redsum[tx * 8 + j], csum[j]);
        atomicAdd(&redsq [tx * 8 + j], csq [j]);
    }
    __syncthreads();
    if (tid < 128) {
        atomicAdd(&gsum[n0 + tid], redsum[tid]);
        atomicAdd(&gsq [n0 + tid], redsq [tid]);
    }
}

// ---------------------------------------------------------------------------
// Kernel 3/5: finalize BN stats -> per-channel scale s, shift t
//   y_norm = y*s + t,  s = gamma*rsqrt(var+eps),  t = beta - mean*s
// ---------------------------------------------------------------------------
template <bool SECOND>
__global__ void finalize_kernel(const float* __restrict__ gamma,
                                const float* __restrict__ beta)
{
    constexpr int C = SECOND ? M2_ : M1_;
    const int c = threadIdx.x;
    if (c < C) {
        const float* gsum = SECOND ? g_sum2 : g_sum1;
        const float* gsq  = SECOND ? g_sq2  : g_sq1;
        float* s          = SECOND ? g_s2   : g_s1;
        float* t          = SECOND ? g_t2   : g_t1;
        const float invC = 1.0f / (float)MROWS;
        float mean = gsum[c] * invC;
        float var  = gsq[c] * invC - mean * mean;
        float rs   = rsqrtf(var + 1e-5f);
        float sc   = gamma[c] * rs;
        s[c] = sc;
        t[c] = fmaf(-mean, sc, beta[c]);
    }
}

// ---------------------------------------------------------------------------
// Kernel 6: final BN2 + ReLU, in-place on d_out  [MROWS, 128]
// ---------------------------------------------------------------------------
__global__ void bn_out_kernel(float* __restrict__ out)
{
    const size_t idx = (size_t)blockIdx.x * blockDim.x + threadIdx.x;  // float4 idx
    float4 v = ((float4*)out)[idx];
    const int c = ((int)(idx * 4)) & (M2_ - 1);
    v.x = fmaxf(fmaf(v.x, g_s2[c + 0], g_t2[c + 0]), 0.f);
    v.y = fmaxf(fmaf(v.y, g_s2[c + 1], g_t2[c + 1]), 0.f);
    v.z = fmaxf(fmaf(v.z, g_s2[c + 2], g_t2[c + 2]), 0.f);
    v.w = fmaxf(fmaf(v.w, g_s2[c + 3], g_t2[c + 3]), 0.f);
    ((float4*)out)[idx] = v;
}

// ---------------------------------------------------------------------------
// Launch
// ---------------------------------------------------------------------------
extern "C" void kernel_launch(void* const* d_in, const int* in_sizes, int n_in,
                              void* d_out, int out_size)
{
    const float* txyz   = (const float*)d_in[0];
    const float* sxyz   = (const float*)d_in[1];
    const float* sfeat  = (const float*)d_in[2];
    const float* skip   = (const float*)d_in[3];
    const float* W1     = (const float*)d_in[4];
    const float* gamma1 = (const float*)d_in[5];
    const float* beta1  = (const float*)d_in[6];
    const float* W2     = (const float*)d_in[7];
    const float* gamma2 = (const float*)d_in[8];
    const float* beta2  = (const float*)d_in[9];
    float* out = (float*)d_out;

    zero_stats_kernel<<<1, 256>>>();
    interp_concat_kernel<<<dim3(N_ / 128, B_), 128>>>(txyz, sxyz, sfeat, skip);
    gemm_bn_kernel<false><<<dim3(M1_ / 128, MROWS / 128), 256>>>(W1, nullptr);
    finalize_kernel<false><<<1, 256>>>(gamma1, beta1);
    gemm_bn_kernel<true><<<dim3(M2_ / 128, MROWS / 128), 256>>>(W2, out);
    finalize_kernel<true><<<1, 128>>>(gamma2, beta2);
    bn_out_kernel<<<(MROWS * M2_ / 4) / 256, 256>>>(out);
}

// round 7
// speedup vs baseline: 1.9235x; 1.9235x over previous
#include <cuda_runtime.h>
#include <cuda_bf16.h>
#include <cstdint>

// Problem shape (fixed for this instance)
#define B_    16
#define N_    4096
#define S_    1024
#define C2_   256
#define C1_   128
#define CIN_  384      // C2_ + C1_
#define M1_   256
#define M2_   128
#define MROWS (B_ * N_)   // 65536

// ---------------------------------------------------------------------------
// Scratch (static __device__ globals)
// ---------------------------------------------------------------------------
__device__ __nv_bfloat16 g_xh[(size_t)MROWS * CIN_];  // concat input hi plane
__device__ __nv_bfloat16 g_xl[(size_t)MROWS * CIN_];  // concat input lo plane
__device__ float g_y1[(size_t)MROWS * M1_];           // raw conv1 output fp32
__device__ __nv_bfloat16 g_w1h[M1_ * CIN_], g_w1l[M1_ * CIN_];
__device__ __nv_bfloat16 g_w2h[M2_ * M1_],  g_w2l[M2_ * M1_];
__device__ float g_sum1[M1_], g_sq1[M1_], g_s1[M1_], g_t1[M1_];
__device__ float g_sum2[M2_], g_sq2[M2_], g_s2[M2_], g_t2[M2_];

// ---------------------------------------------------------------------------
// PTX helpers — all baseline compute_80-level (no arch-specific features)
// ---------------------------------------------------------------------------
__device__ __forceinline__ unsigned smem_u32(const void* p) {
    unsigned a;
    asm("{ .reg .u64 t; cvta.to.shared.u64 t, %1; cvt.u32.u64 %0, t; }"
        : "=r"(a) : "l"(p));
    return a;
}
__device__ __forceinline__ void cp16(unsigned dst, const void* src) {
    asm volatile("cp.async.cg.shared.global [%0], [%1], 16;"
                 :: "r"(dst), "l"(src) : "memory");
}
__device__ __forceinline__ void cp_commit() {
    asm volatile("cp.async.commit_group;" ::: "memory");
}
__device__ __forceinline__ void cp_wait_all() {
    asm volatile("cp.async.wait_group 0;" ::: "memory");
}
__device__ __forceinline__ void ldsm4(unsigned* r, unsigned addr) {
    asm volatile("ldmatrix.sync.aligned.m8n8.x4.shared.b16 {%0,%1,%2,%3}, [%4];"
                 : "=r"(r[0]), "=r"(r[1]), "=r"(r[2]), "=r"(r[3]) : "r"(addr));
}
__device__ __forceinline__ void mma16816(float* d, const unsigned* a,
                                         unsigned b0, unsigned b1) {
    asm volatile(
        "mma.sync.aligned.m16n8k16.row.col.f32.bf16.bf16.f32 "
        "{%0,%1,%2,%3}, {%4,%5,%6,%7}, {%8,%9}, {%0,%1,%2,%3};"
        : "+f"(d[0]), "+f"(d[1]), "+f"(d[2]), "+f"(d[3])
        : "r"(a[0]), "r"(a[1]), "r"(a[2]), "r"(a[3]), "r"(b0), "r"(b1));
}
__device__ __forceinline__ unsigned pack2(__nv_bfloat16 lo, __nv_bfloat16 hi) {
    return ((unsigned)__bfloat16_as_ushort(hi) << 16) |
           (unsigned)__bfloat16_as_ushort(lo);
}

// ---------------------------------------------------------------------------
// Kernel: zero BN stats + split W1/W2 into bf16 hi/lo planes
// ---------------------------------------------------------------------------
__global__ void prep_kernel(const float* __restrict__ W1, const float* __restrict__ W2) {
    const int idx = blockIdx.x * 256 + threadIdx.x;
    if (blockIdx.x == 0) {
        const int t = threadIdx.x;
        if (t < M1_) { g_sum1[t] = 0.f; g_sq1[t] = 0.f; }
        if (t < M2_) { g_sum2[t] = 0.f; g_sq2[t] = 0.f; }
    }
    if (idx < M1_ * CIN_) {
        float w = W1[idx];
        __nv_bfloat16 h = __float2bfloat16(w);
        g_w1h[idx] = h;
        g_w1l[idx] = __float2bfloat16(w - __bfloat162float(h));
    } else {
        const int j = idx - M1_ * CIN_;
        if (j < M2_ * M1_) {
            float w = W2[j];
            __nv_bfloat16 h = __float2bfloat16(w);
            g_w2h[j] = h;
            g_w2l[j] = __float2bfloat16(w - __bfloat162float(h));
        }
    }
}

// ---------------------------------------------------------------------------
// Kernel: 3-NN interpolation + concat -> split bf16 planes g_xh/g_xl
// ---------------------------------------------------------------------------
__global__ void interp_concat_kernel(const float* __restrict__ txyz,
                                     const float* __restrict__ sxyz,
                                     const float* __restrict__ sfeat,
                                     const float* __restrict__ skip)
{
    __shared__ float4 s_src[S_];
    __shared__ float  s_w[3][128];
    __shared__ int    s_i[3][128];

    const int b   = blockIdx.y;
    const int p0  = blockIdx.x * 128;
    const int tid = threadIdx.x;

    const float* sx = sxyz + (size_t)b * S_ * 3;
    for (int i = tid; i < S_; i += 128) {
        float x = sx[i * 3 + 0], y = sx[i * 3 + 1], z = sx[i * 3 + 2];
        s_src[i] = make_float4(x, y, z, x * x + y * y + z * z);
    }
    __syncthreads();

    const int n = p0 + tid;
    const float* tp = txyz + ((size_t)b * N_ + n) * 3;
    const float tx0 = tp[0], ty0 = tp[1], tz0 = tp[2];
    const float q2 = tx0 * tx0 + ty0 * ty0 + tz0 * tz0;

    float d0 = 3.4e38f, d1 = 3.4e38f, d2 = 3.4e38f;
    int   i0 = 0, i1 = 0, i2 = 0;
    #pragma unroll 4
    for (int s = 0; s < S_; ++s) {
        float4 v = s_src[s];
        float cr   = tx0 * v.x + ty0 * v.y + tz0 * v.z;
        float dist = fmaxf(q2 + v.w - 2.f * cr, 0.f);
        if (dist < d2) {
            if (dist < d1) {
                d2 = d1; i2 = i1;
                if (dist < d0) { d1 = d0; i1 = i0; d0 = dist; i0 = s; }
                else           { d1 = dist; i1 = s; }
            } else { d2 = dist; i2 = s; }
        }
    }

    int   ii[3] = { i0, i1, i2 };
    float w[3];
    float wsum = 0.f;
    #pragma unroll
    for (int k = 0; k < 3; ++k) {
        float4 v = s_src[ii[k]];
        float dx = tx0 - v.x, dy = ty0 - v.y, dz = tz0 - v.z;
        float dd = dx * dx + dy * dy + dz * dz;
        w[k] = 1.f / (dd + 1e-8f);
        wsum += w[k];
    }
    float inv = 1.f / wsum;
    #pragma unroll
    for (int k = 0; k < 3; ++k) { s_w[k][tid] = w[k] * inv; s_i[k][tid] = ii[k]; }
    __syncthreads();

    const float* F = sfeat + (size_t)b * S_ * C2_;
    for (int p = 0; p < 128; ++p) {
        const float w0 = s_w[0][p], w1 = s_w[1][p], w2 = s_w[2][p];
        const float* f0 = F + (size_t)s_i[0][p] * C2_;
        const float* f1 = F + (size_t)s_i[1][p] * C2_;
        const float* f2 = F + (size_t)s_i[2][p] * C2_;
        const size_t row = (size_t)b * N_ + p0 + p;
        __nv_bfloat16* xh = g_xh + row * CIN_;
        __nv_bfloat16* xl = g_xl + row * CIN_;

        #pragma unroll
        for (int half = 0; half < 2; ++half) {
            const int c = tid + half * 128;
            float v = w0 * f0[c] + w1 * f1[c] + w2 * f2[c];
            __nv_bfloat16 h = __float2bfloat16(v);
            xh[c] = h;
            xl[c] = __float2bfloat16(v - __bfloat162float(h));
        }
        {
            float v = skip[row * C1_ + tid];
            __nv_bfloat16 h = __float2bfloat16(v);
            xh[256 + tid] = h;
            xl[256 + tid] = __float2bfloat16(v - __bfloat162float(h));
        }
    }
}

// ---------------------------------------------------------------------------
// mma.sync GEMM: C[M, NOUT] = T(A)[M, K] * W[NOUT, K]^T   (split-bf16, 3 HMMA/k16)
//   FIRST : A = (g_xh, g_xl) bf16 planes via cp.async; C = g_y1; stats -> sum1/sq1
//   SECOND: A = g_y1 fp32 -> relu(a*s1+t1) -> split in producer; C = out; stats2
// Block tile 128(M) x 128(N) x 32(K), 256 thr = 8 warps (2 M x 4 N), warp 64x32.
// Smem rows: 32 bf16 + 8 pad = 80 B  (bank-conflict-free ldmatrix).
// ---------------------------------------------------------------------------
#define PLANE_  (128 * 80)          // one tile plane (A or B, hi or lo)
#define STAGE_  (4 * PLANE_)        // Ah, Al, Bh, Bl
#define RED_OFF (2 * STAGE_)        // 81920
#define SC_OFF  (RED_OFF + 1024)

template <int K, int NOUT, bool SECOND>
__global__ void __launch_bounds__(256, 2)
gemm_mma_kernel(float* __restrict__ outp)
{
    constexpr int NC = K / 32;

    extern __shared__ char sm[];
    const unsigned sb = smem_u32(sm);

    const int tid  = threadIdx.x;
    const int wid  = tid >> 5;
    const int lane = tid & 31;
    const int warpM = wid & 1;       // 2 warps over M
    const int warpN = wid >> 1;      // 4 warps over N
    const int n0 = blockIdx.x * 128;
    const size_t m0 = (size_t)blockIdx.y * 128;

    const float* Af = g_y1;                          // SECOND source (fp32)
    float* C    = SECOND ? outp : g_y1;
    const __nv_bfloat16* Ah = g_xh;                  // FIRST source planes
    const __nv_bfloat16* Al = g_xl;
    const __nv_bfloat16* Wh = SECOND ? g_w2h : g_w1h;
    const __nv_bfloat16* Wl = SECOND ? g_w2l : g_w1l;
    float* gsum = SECOND ? g_sum2 : g_sum1;
    float* gsq  = SECOND ? g_sq2  : g_sq1;

    float* redsum = (float*)(sm + RED_OFF);
    float* redsq  = redsum + 128;
    float* s_sc   = (float*)(sm + SC_OFF);
    float* s_sh   = s_sc + K;

    if (tid < 128) { redsum[tid] = 0.f; redsq[tid] = 0.f; }
    if (SECOND && tid < K) { s_sc[tid] = g_s1[tid]; s_sh[tid] = g_t1[tid]; }
    __syncthreads();

    // ---- producers -------------------------------------------------------
    auto produceB = [&](int buf, int kc) {
        const int r = tid >> 2, c = tid & 3;        // 64 rows x 4 chunks / pass
        const unsigned bh = sb + buf * STAGE_ + 2 * PLANE_;
        #pragma unroll
        for (int s = 0; s < 2; ++s) {
            const int row = r + 64 * s;
            const size_t g = (size_t)(n0 + row) * K + kc * 32 + c * 8;
            const unsigned d = bh + row * 80 + c * 16;
            cp16(d,          Wh + g);
            cp16(d + PLANE_, Wl + g);
        }
    };
    auto produceA1 = [&](int buf, int kc) {         // FIRST: cp.async planes
        const int r = tid >> 2, c = tid & 3;
        const unsigned ah = sb + buf * STAGE_;
        #pragma unroll
        for (int s = 0; s < 2; ++s) {
            const int row = r + 64 * s;
            const size_t g = (m0 + row) * CIN_ + kc * 32 + c * 8;
            const unsigned d = ah + row * 80 + c * 16;
            cp16(d,          Ah + g);
            cp16(d + PLANE_, Al + g);
        }
    };
    auto produceA2 = [&](int buf, int kc) {         // SECOND: LDG+BN+ReLU+split+STS
        const int r = tid >> 1, half = tid & 1;     // 128 rows x 2 halves(16 floats)
        const int kk = kc * 32 + half * 16;
        const float* src = Af + (m0 + r) * K + kk;
        unsigned hi[8], lo[8];
        #pragma unroll
        for (int q = 0; q < 4; ++q) {
            float4 v = *(const float4*)(src + q * 4);
            const int kb = kk + q * 4;
            v.x = fmaxf(fmaf(v.x, s_sc[kb + 0], s_sh[kb + 0]), 0.f);
            v.y = fmaxf(fmaf(v.y, s_sc[kb + 1], s_sh[kb + 1]), 0.f);
            v.z = fmaxf(fmaf(v.z, s_sc[kb + 2], s_sh[kb + 2]), 0.f);
            v.w = fmaxf(fmaf(v.w, s_sc[kb + 3], s_sh[kb + 3]), 0.f);
            __nv_bfloat16 h0 = __float2bfloat16(v.x), h1 = __float2bfloat16(v.y);
            __nv_bfloat16 h2 = __float2bfloat16(v.z), h3 = __float2bfloat16(v.w);
            hi[q * 2 + 0] = pack2(h0, h1);
            hi[q * 2 + 1] = pack2(h2, h3);
            lo[q * 2 + 0] = pack2(__float2bfloat16(v.x - __bfloat162float(h0)),
                                  __float2bfloat16(v.y - __bfloat162float(h1)));
            lo[q * 2 + 1] = pack2(__float2bfloat16(v.z - __bfloat162float(h2)),
                                  __float2bfloat16(v.w - __bfloat162float(h3)));
        }
        char* ah = sm + buf * STAGE_ + r * 80 + half * 32;
        *(uint4*)(ah +  0)          = make_uint4(hi[0], hi[1], hi[2], hi[3]);
        *(uint4*)(ah + 16)          = make_uint4(hi[4], hi[5], hi[6], hi[7]);
        *(uint4*)(ah + PLANE_ +  0) = make_uint4(lo[0], lo[1], lo[2], lo[3]);
        *(uint4*)(ah + PLANE_ + 16) = make_uint4(lo[4], lo[5], lo[6], lo[7]);
    };
    auto produce = [&](int buf, int kc) {
        produceB(buf, kc);
        if (SECOND) produceA2(buf, kc); else produceA1(buf, kc);
    };

    // ---- ldmatrix per-lane base offsets ----------------------------------
    const unsigned aRowOff =
        (unsigned)((warpM * 64 + (lane & 15)) * 80 + ((lane >> 4) & 1) * 16);
    const unsigned bRowOff =
        (unsigned)((warpN * 32 + ((lane >> 4) << 3) + (lane & 7)) * 80 +
                   ((lane >> 3) & 1) * 16);

    float acc[4][4][4];
    #pragma unroll
    for (int i = 0; i < 4; ++i)
        #pragma unroll
        for (int j = 0; j < 4; ++j)
            #pragma unroll
            for (int q = 0; q < 4; ++q) acc[i][j][q] = 0.f;

    produce(0, 0);
    cp_commit();

    for (int kc = 0; kc < NC; ++kc) {
        cp_wait_all();
        __syncthreads();
        if (kc + 1 < NC) produce(kc & 1 ? 0 : 1, kc + 1);
        cp_commit();

        const unsigned base = sb + (kc & 1) * STAGE_;
        const unsigned aH = base + aRowOff;
        const unsigned aL = aH + PLANE_;
        const unsigned bH = base + 2 * PLANE_ + bRowOff;
        const unsigned bL = bH + PLANE_;

        #pragma unroll
        for (int k16 = 0; k16 < 2; ++k16) {
            const unsigned ko = k16 * 32;
            unsigned bh[8], bl[8];
            ldsm4(bh + 0, bH + ko);
            ldsm4(bh + 4, bH + ko + 16 * 80);
            ldsm4(bl + 0, bL + ko);
            ldsm4(bl + 4, bL + ko + 16 * 80);
            #pragma unroll
            for (int i = 0; i < 4; ++i) {
                unsigned ah[4], al[4];
                ldsm4(ah, aH + ko + i * (16 * 80));
                ldsm4(al, aL + ko + i * (16 * 80));
                #pragma unroll
                for (int j = 0; j < 4; ++j) {
                    mma16816(acc[i][j], ah, bh[2 * j], bh[2 * j + 1]);
                    mma16816(acc[i][j], ah, bl[2 * j], bl[2 * j + 1]);
                    mma16816(acc[i][j], al, bh[2 * j], bh[2 * j + 1]);
                }
            }
        }
    }

    // ---- epilogue: regs -> smem C-tile -> coalesced store + BN stats -----
    __syncthreads();                      // all tile reads done; reuse smem
    float* Ct = (float*)sm;               // 128 x 132 fp32 (67.6 KB)
    const int g = lane >> 2, q = lane & 3;
    #pragma unroll
    for (int i = 0; i < 4; ++i) {
        const int r0 = warpM * 64 + i * 16 + g;
        #pragma unroll
        for (int j = 0; j < 4; ++j) {
            const int c0 = warpN * 32 + j * 8 + q * 2;
            *(float2*)&Ct[r0 * 132 + c0]       = make_float2(acc[i][j][0], acc[i][j][1]);
            *(float2*)&Ct[(r0 + 8) * 132 + c0] = make_float2(acc[i][j][2], acc[i][j][3]);
        }
    }
    __syncthreads();

    float4 s4 = make_float4(0, 0, 0, 0), q4 = make_float4(0, 0, 0, 0);
    const int cc = (tid & 31) * 4;
    #pragma unroll
    for (int p = 0; p < 16; ++p) {
        const int idx = tid + p * 256;
        const int row = idx >> 5;
        float4 v = *(float4*)&Ct[row * 132 + cc];
        *(float4*)(C + (m0 + row) * NOUT + n0 + cc) = v;
        s4.x += v.x; s4.y += v.y; s4.z += v.z; s4.w += v.w;
        q4.x = fmaf(v.x, v.x, q4.x); q4.y = fmaf(v.y, v.y, q4.y);
        q4.z = fmaf(v.z, v.z, q4.z); q4.w = fmaf(v.w, v.w, q4.w);
    }
    atomicAdd(&redsum[cc + 0], s4.x); atomicAdd(&redsum[cc + 1], s4.y);
    atomicAdd(&redsum[cc + 2], s4.z); atomicAdd(&redsum[cc + 3], s4.w);
    atomicAdd(&redsq [cc + 0], q4.x); atomicAdd(&redsq [cc + 1], q4.y);
    atomicAdd(&redsq [cc + 2], q4.z); atomicAdd(&redsq [cc + 3], q4.w);
    __syncthreads();
    if (tid < 128) {
        atomicAdd(&gsum[n0 + tid], redsum[tid]);
        atomicAdd(&gsq [n0 + tid], redsq [tid]);
    }
}

// ---------------------------------------------------------------------------
// finalize BN stats -> per-channel scale s, shift t
// ---------------------------------------------------------------------------
template <bool SECOND>
__global__ void finalize_kernel(const float* __restrict__ gamma,
                                const float* __restrict__ beta)
{
    constexpr int C = SECOND ? M2_ : M1_;
    const int c = threadIdx.x;
    if (c < C) {
        const float* gsum = SECOND ? g_sum2 : g_sum1;
        const float* gsq  = SECOND ? g_sq2  : g_sq1;
        float* s          = SECOND ? g_s2   : g_s1;
        float* t          = SECOND ? g_t2   : g_t1;
        const float invC = 1.0f / (float)MROWS;
        float mean = gsum[c] * invC;
        float var  = gsq[c] * invC - mean * mean;
        float rs   = rsqrtf(var + 1e-5f);
        float sc   = gamma[c] * rs;
        s[c] = sc;
        t[c] = fmaf(-mean, sc, beta[c]);
    }
}

// ---------------------------------------------------------------------------
// final BN2 + ReLU, in-place on d_out [MROWS, 128]
// ---------------------------------------------------------------------------
__global__ void bn_out_kernel(float* __restrict__ out)
{
    const size_t idx = (size_t)blockIdx.x * blockDim.x + threadIdx.x;  // float4 idx
    float4 v = ((float4*)out)[idx];
    const int c = ((int)(idx * 4)) & (M2_ - 1);
    v.x = fmaxf(fmaf(v.x, g_s2[c + 0], g_t2[c + 0]), 0.f);
    v.y = fmaxf(fmaf(v.y, g_s2[c + 1], g_t2[c + 1]), 0.f);
    v.z = fmaxf(fmaf(v.z, g_s2[c + 2], g_t2[c + 2]), 0.f);
    v.w = fmaxf(fmaf(v.w, g_s2[c + 3], g_t2[c + 3]), 0.f);
    ((float4*)out)[idx] = v;
}

// ---------------------------------------------------------------------------
// Launch
// ---------------------------------------------------------------------------
extern "C" void kernel_launch(void* const* d_in, const int* in_sizes, int n_in,
                              void* d_out, int out_size)
{
    const float* txyz   = (const float*)d_in[0];
    const float* sxyz   = (const float*)d_in[1];
    const float* sfeat  = (const float*)d_in[2];
    const float* skip   = (const float*)d_in[3];
    const float* W1     = (const float*)d_in[4];
    const float* gamma1 = (const float*)d_in[5];
    const float* beta1  = (const float*)d_in[6];
    const float* W2     = (const float*)d_in[7];
    const float* gamma2 = (const float*)d_in[8];
    const float* beta2  = (const float*)d_in[9];
    float* out = (float*)d_out;

    const int SMEM_SZ = SC_OFF + 2 * M1_ * 4;   // 81920 + 1024 + 2048 = 84992
    cudaFuncSetAttribute(gemm_mma_kernel<CIN_, M1_, false>,
                         cudaFuncAttributeMaxDynamicSharedMemorySize, SMEM_SZ);
    cudaFuncSetAttribute(gemm_mma_kernel<M1_, M2_, true>,
                         cudaFuncAttributeMaxDynamicSharedMemorySize, SMEM_SZ);

    prep_kernel<<<512, 256>>>(W1, W2);
    interp_concat_kernel<<<dim3(N_ / 128, B_), 128>>>(txyz, sxyz, sfeat, skip);
    // grid.x = n-tile (fastest) so both N-tiles of an M-tile share A via L2
    gemm_mma_kernel<CIN_, M1_, false><<<dim3(M1_ / 128, MROWS / 128), 256, SMEM_SZ>>>(nullptr);
    finalize_kernel<false><<<1, 256>>>(gamma1, beta1);
    gemm_mma_kernel<M1_, M2_, true><<<dim3(M2_ / 128, MROWS / 128), 256, SMEM_SZ>>>(out);
    finalize_kernel<true><<<1, 128>>>(gamma2, beta2);
    bn_out_kernel<<<(MROWS * M2_ / 4) / 256, 256>>>(out);
}